// round 7
// baseline (speedup 1.0000x reference)
#include <cuda_runtime.h>
#include <stdint.h>

#define Nn 100000
#define Ee 1600000
#define EAd 7
#define Hd 64
#define Ld 32
#define Gg 512
#define Cc 6

// ---------------- scratch ----------------
__device__ __align__(256) float g_agg1[Nn];
__device__ __align__(256) float g_h1[Nn * Hd];
__device__ __align__(256) float g_agg2[Nn * Hd];

// ---------------- Threefry-2x32 partitionable (JAX >= 0.4.36 default) ----------------
__device__ __forceinline__ float tf_normal(unsigned j) {
    unsigned x0 = 0u;       // counts_hi
    unsigned x1 = j;        // counts_lo
    const unsigned k0 = 0u, k1 = 42u;
    const unsigned k2 = k0 ^ k1 ^ 0x1BD11BDAu;
    x0 += k0; x1 += k1;
    const int R0[4] = {13, 15, 26, 6};
    const int R1[4] = {17, 29, 16, 24};
#pragma unroll
    for (int i = 0; i < 5; i++) {
#pragma unroll
        for (int r = 0; r < 4; r++) {
            int rr = ((i & 1) == 0) ? R0[r] : R1[r];
            x0 += x1;
            x1 = (x1 << rr) | (x1 >> (32 - rr));
            x1 ^= x0;
        }
        unsigned a0 = (i % 3 == 0) ? k1 : (i % 3 == 1) ? k2 : k0;
        unsigned a1 = (i % 3 == 0) ? k2 : (i % 3 == 1) ? k0 : k1;
        x0 += a0;
        x1 += a1 + (unsigned)(i + 1);
    }
    unsigned bits = x0 ^ x1;

    float f = __fadd_rn(__uint_as_float((bits >> 9) | 0x3f800000u), -1.0f);
    const float lo = -0.99999994f;
    float u = __fadd_rn(__fmul_rn(f, 2.0f), lo);
    u = fmaxf(u, lo);

    float w = -log1pf(-u * u);
    float p;
    if (w < 5.0f) {
        w -= 2.5f;
        p = 2.81022636e-08f;
        p = fmaf(p, w, 3.43273939e-07f);
        p = fmaf(p, w, -3.5233877e-06f);
        p = fmaf(p, w, -4.39150654e-06f);
        p = fmaf(p, w, 0.00021858087f);
        p = fmaf(p, w, -0.00125372503f);
        p = fmaf(p, w, -0.00417768164f);
        p = fmaf(p, w, 0.246640727f);
        p = fmaf(p, w, 1.50140941f);
    } else {
        w = sqrtf(w) - 3.0f;
        p = -0.000200214257f;
        p = fmaf(p, w, 0.000100950558f);
        p = fmaf(p, w, 0.00134934322f);
        p = fmaf(p, w, -0.00367342844f);
        p = fmaf(p, w, 0.00573950773f);
        p = fmaf(p, w, -0.0076224613f);
        p = fmaf(p, w, 0.00943887047f);
        p = fmaf(p, w, 1.00167406f);
        p = fmaf(p, w, 2.83297682f);
    }
    return 1.41421356f * (p * u);
}

// ---------------- kernels ----------------
__global__ void k_zero() {
    int i = blockIdx.x * blockDim.x + threadIdx.x;
    const int tot = (Nn + Nn * Hd) / 4;
    if (i < tot) {
        float4 z = make_float4(0.f, 0.f, 0.f, 0.f);
        if (i < Nn / 4) ((float4*)g_agg1)[i] = z;
        else            ((float4*)g_agg2)[i - Nn / 4] = z;
    }
}

// conv1 edge: 4 edges/thread; ea via 7x LDG.128, ei via 2x int4
__global__ void k_conv1_edge(const float* __restrict__ x, const int* __restrict__ ei,
                             const float* __restrict__ ea, const float* __restrict__ We1,
                             const float* __restrict__ be1) {
    int g4 = blockIdx.x * blockDim.x + threadIdx.x;
    if (g4 >= Ee / 4) return;
    int e0 = g4 * 4;

    float w[EAd];
#pragma unroll
    for (int i = 0; i < EAd; i++) w[i] = __ldg(We1 + i);
    float be = __ldg(be1);

    float A[28];
    const float4* ap = (const float4*)(ea + (long long)e0 * EAd);
#pragma unroll
    for (int i = 0; i < 7; i++) *((float4*)&A[i * 4]) = __ldg(ap + i);

    int4 ss = *(const int4*)(ei + e0);
    int4 dd = *(const int4*)(ei + Ee + e0);
    int sv[4] = {ss.x, ss.y, ss.z, ss.w};
    int dv[4] = {dd.x, dd.y, dd.z, dd.w};

#pragma unroll
    for (int j = 0; j < 4; j++) {
        float acc = be;
#pragma unroll
        for (int i = 0; i < EAd; i++) acc = fmaf(A[j * EAd + i], w[i], acc);
        float m = fmaxf(__ldg(x + sv[j]) + acc, 0.f);
        atomicAdd(&g_agg1[dv[j]], m);
    }
}

// conv1 node MLP
__global__ void k_conv1_mlp(const float* __restrict__ x, const float* __restrict__ W11,
                            const float* __restrict__ b11, const float* __restrict__ W12,
                            const float* __restrict__ b12, const float* __restrict__ eps1) {
    __shared__ float tS[8 * Hd];
    int k = threadIdx.x;  // 64
    float wcol[Hd];
#pragma unroll
    for (int j = 0; j < Hd; j++) wcol[j] = __ldg(W12 + j * Hd + k);

    int n0 = blockIdx.x * 8;
    float ep = 1.f + *eps1;
    float w11k = __ldg(W11 + k), b11k = __ldg(b11 + k);
#pragma unroll
    for (int i = 0; i < 8; i++) {
        float a = ep * __ldg(x + n0 + i) + g_agg1[n0 + i];
        tS[i * Hd + k] = fmaxf(a * w11k + b11k, 0.f);
    }
    __syncthreads();
    float acc[8];
    float bk = __ldg(b12 + k);
#pragma unroll
    for (int i = 0; i < 8; i++) acc[i] = bk;
#pragma unroll
    for (int jq = 0; jq < Hd / 4; jq++) {
#pragma unroll
        for (int i = 0; i < 8; i++) {
            float4 v = *(const float4*)&tS[i * Hd + jq * 4];
            acc[i] = fmaf(v.x, wcol[jq * 4 + 0], acc[i]);
            acc[i] = fmaf(v.y, wcol[jq * 4 + 1], acc[i]);
            acc[i] = fmaf(v.z, wcol[jq * 4 + 2], acc[i]);
            acc[i] = fmaf(v.w, wcol[jq * 4 + 3], acc[i]);
        }
    }
#pragma unroll
    for (int i = 0; i < 8; i++)
        g_h1[(long long)(n0 + i) * Hd + k] = fmaxf(acc[i], 0.f);
}

// conv2 edge v4: 32 lanes/edge, float2 weights (16 regs), 8 CTAs/SM
__global__ void __launch_bounds__(256, 8) k_conv2_edge(
        const int* __restrict__ ei, const float* __restrict__ ea,
        const float* __restrict__ We2, const float* __restrict__ be2) {
    int t = threadIdx.x;  // 256
    int lane = t & 31;
    int c0 = lane * 2;
    float2 wr[EAd];
#pragma unroll
    for (int i = 0; i < EAd; i++) wr[i] = *(const float2*)&We2[i * Hd + c0];
    float2 br = *(const float2*)&be2[c0];

    int group = (blockIdx.x * 256 + t) >> 5;
    int nGroups = (gridDim.x * 256) >> 5;
    for (int e = group; e < Ee; e += nGroups) {
        int s = __ldg(ei + e);
        int d = __ldg(ei + Ee + e);
        float2 p = br;
        const float* a = ea + (long long)e * EAd;
#pragma unroll
        for (int i = 0; i < EAd; i++) {
            float av = __ldg(a + i);
            p.x = fmaf(av, wr[i].x, p.x);
            p.y = fmaf(av, wr[i].y, p.y);
        }
        float2 h = *(const float2*)(g_h1 + (long long)s * Hd + c0);
        float2 m;
        m.x = fmaxf(h.x + p.x, 0.f);
        m.y = fmaxf(h.y + p.y, 0.f);
        float* dst = g_agg2 + (long long)d * Hd + c0;
        asm volatile("red.global.add.v2.f32 [%0], {%1,%2};"
                     :: "l"(dst), "f"(m.x), "f"(m.y) : "memory");
    }
}

// conv2 node MLP + heads
__global__ void k_conv2_mlp(const float* __restrict__ W21, const float* __restrict__ b21,
                            const float* __restrict__ W22, const float* __restrict__ b22,
                            const float* __restrict__ eps2, const float* __restrict__ Wmu,
                            const float* __restrict__ bmu, const float* __restrict__ Wlv,
                            const float* __restrict__ blv, float* __restrict__ outz,
                            float* __restrict__ outmu, float* __restrict__ outlv) {
    __shared__ float bufA[8 * Hd];
    __shared__ float bufB[8 * Hd];
    int k = threadIdx.x;  // 64
    int n0 = blockIdx.x * 8;
    float ep = 1.f + *eps2;

    float wcol[Hd];
#pragma unroll
    for (int j = 0; j < Hd; j++) wcol[j] = __ldg(W21 + j * Hd + k);

#pragma unroll
    for (int i = 0; i < 8; i++) {
        long long o = (long long)(n0 + i) * Hd + k;
        bufA[i * Hd + k] = ep * g_h1[o] + g_agg2[o];
    }
    __syncthreads();

    float acc[8];
    float b = __ldg(b21 + k);
#pragma unroll
    for (int i = 0; i < 8; i++) acc[i] = b;
#pragma unroll
    for (int jq = 0; jq < Hd / 4; jq++) {
#pragma unroll
        for (int i = 0; i < 8; i++) {
            float4 v = *(const float4*)&bufA[i * Hd + jq * 4];
            acc[i] = fmaf(v.x, wcol[jq * 4 + 0], acc[i]);
            acc[i] = fmaf(v.y, wcol[jq * 4 + 1], acc[i]);
            acc[i] = fmaf(v.z, wcol[jq * 4 + 2], acc[i]);
            acc[i] = fmaf(v.w, wcol[jq * 4 + 3], acc[i]);
        }
    }
#pragma unroll
    for (int i = 0; i < 8; i++) bufB[i * Hd + k] = fmaxf(acc[i], 0.f);

#pragma unroll
    for (int j = 0; j < Hd; j++) wcol[j] = __ldg(W22 + j * Hd + k);
    __syncthreads();

    b = __ldg(b22 + k);
#pragma unroll
    for (int i = 0; i < 8; i++) acc[i] = b;
#pragma unroll
    for (int jq = 0; jq < Hd / 4; jq++) {
#pragma unroll
        for (int i = 0; i < 8; i++) {
            float4 v = *(const float4*)&bufB[i * Hd + jq * 4];
            acc[i] = fmaf(v.x, wcol[jq * 4 + 0], acc[i]);
            acc[i] = fmaf(v.y, wcol[jq * 4 + 1], acc[i]);
            acc[i] = fmaf(v.z, wcol[jq * 4 + 2], acc[i]);
            acc[i] = fmaf(v.w, wcol[jq * 4 + 3], acc[i]);
        }
    }
    __syncthreads();
#pragma unroll
    for (int i = 0; i < 8; i++) bufA[i * Hd + k] = fmaxf(acc[i], 0.f);  // h2

    int l = k & 31;
    const float* Wh = (k < 32) ? Wmu : Wlv;
#pragma unroll
    for (int j = 0; j < Hd; j++) wcol[j] = __ldg(Wh + j * Ld + l);
    __syncthreads();

    b = (k < 32) ? __ldg(bmu + l) : __ldg(blv + l);
#pragma unroll
    for (int i = 0; i < 8; i++) acc[i] = b;
#pragma unroll
    for (int jq = 0; jq < Hd / 4; jq++) {
#pragma unroll
        for (int i = 0; i < 8; i++) {
            float4 v = *(const float4*)&bufA[i * Hd + jq * 4];
            acc[i] = fmaf(v.x, wcol[jq * 4 + 0], acc[i]);
            acc[i] = fmaf(v.y, wcol[jq * 4 + 1], acc[i]);
            acc[i] = fmaf(v.z, wcol[jq * 4 + 2], acc[i]);
            acc[i] = fmaf(v.w, wcol[jq * 4 + 3], acc[i]);
        }
    }
    float* oph = (k < 32) ? outmu : outlv;
#pragma unroll
    for (int i = 0; i < 8; i++) {
        bufB[i * Hd + k] = acc[i];
        oph[(long long)(n0 + i) * Ld + l] = acc[i];
    }
    __syncthreads();

    if (k < 32) {
#pragma unroll
        for (int i = 0; i < 8; i++) {
            float mu = bufB[i * Hd + k];
            float lv = bufB[i * Hd + 32 + k];
            unsigned j = (unsigned)((n0 + i) * Ld + k);
            float z = mu + tf_normal(j) * expf(0.5f * lv);
            outz[(long long)(n0 + i) * Ld + k] = z;
        }
    }
}

// pooling + classifier
__global__ void k_pool(const float* __restrict__ z, const int* __restrict__ batch,
                       const float* __restrict__ Wc, const float* __restrict__ bc,
                       float* __restrict__ logits) {
    int g = blockIdx.x;
    int k = threadIdx.x;  // 32
    __shared__ float emb[Ld];
    __shared__ int bounds[2];
    if (k < 2) {
        int target = g + k;
        int lo = 0, hi = Nn;
        while (lo < hi) {
            int mid = (lo + hi) >> 1;
            if (batch[mid] < target) lo = mid + 1; else hi = mid;
        }
        bounds[k] = lo;
    }
    __syncthreads();
    int s = bounds[0], e = bounds[1];
    float acc = 0.f;
    for (int n = s; n < e; n++) acc += z[(long long)n * Ld + k];
    float cnt = (float)(e - s);
    emb[k] = acc / fmaxf(cnt, 1.f);
    __syncthreads();
    if (k < Cc) {
        float o = __ldg(bc + k);
#pragma unroll
        for (int l = 0; l < Ld; l++) o += emb[l] * __ldg(Wc + l * Cc + k);
        logits[g * Cc + k] = o;
    }
}

// ---------------- launcher ----------------
extern "C" void kernel_launch(void* const* d_in, const int* in_sizes, int n_in,
                              void* d_out, int out_size) {
    const float* x     = (const float*)d_in[0];
    const int*   ei    = (const int*)d_in[1];
    const float* ea    = (const float*)d_in[2];
    const int*   batch = (const int*)d_in[3];
    const float* We1 = (const float*)d_in[4];
    const float* be1 = (const float*)d_in[5];
    const float* W11 = (const float*)d_in[6];
    const float* b11 = (const float*)d_in[7];
    const float* W12 = (const float*)d_in[8];
    const float* b12 = (const float*)d_in[9];
    const float* eps1 = (const float*)d_in[10];
    const float* We2 = (const float*)d_in[11];
    const float* be2 = (const float*)d_in[12];
    const float* W21 = (const float*)d_in[13];
    const float* b21 = (const float*)d_in[14];
    const float* W22 = (const float*)d_in[15];
    const float* b22 = (const float*)d_in[16];
    const float* eps2 = (const float*)d_in[17];
    const float* Wmu = (const float*)d_in[18];
    const float* bmu = (const float*)d_in[19];
    const float* Wlv = (const float*)d_in[20];
    const float* blv = (const float*)d_in[21];
    const float* Wc  = (const float*)d_in[22];
    const float* bc  = (const float*)d_in[23];

    float* out = (float*)d_out;
    float* dz  = out;
    float* dmu = out + (size_t)Nn * Ld;
    float* dlv = out + (size_t)2 * Nn * Ld;
    float* dlg = out + (size_t)3 * Nn * Ld;

    const int ztot = (Nn + Nn * Hd) / 4;
    k_zero<<<(ztot + 255) / 256, 256>>>();
    k_conv1_edge<<<(Ee / 4 + 255) / 256, 256>>>(x, ei, ea, We1, be1);
    k_conv1_mlp<<<Nn / 8, Hd>>>(x, W11, b11, W12, b12, eps1);
    k_conv2_edge<<<1184, 256>>>(ei, ea, We2, be2);
    k_conv2_mlp<<<Nn / 8, Hd>>>(W21, b21, W22, b22, eps2, Wmu, bmu, Wlv, blv, dz, dmu, dlv);
    k_pool<<<Gg, Ld>>>(dz, batch, Wc, bc, dlg);
}

// round 8
// speedup vs baseline: 1.0828x; 1.0828x over previous
#include <cuda_runtime.h>
#include <stdint.h>

#define Nn 100000
#define Ee 1600000
#define EAd 7
#define Hd 64
#define Ld 32
#define Gg 512
#define Cc 6

// ---------------- scratch ----------------
__device__ __align__(256) float g_agg1[Nn];
__device__ __align__(256) float g_h1[Nn * Hd];
__device__ __align__(256) float g_agg2[Nn * Hd];

// ---------------- Threefry-2x32 partitionable (JAX >= 0.4.36 default) ----------------
__device__ __forceinline__ float tf_normal(unsigned j) {
    unsigned x0 = 0u;       // counts_hi
    unsigned x1 = j;        // counts_lo
    const unsigned k0 = 0u, k1 = 42u;
    const unsigned k2 = k0 ^ k1 ^ 0x1BD11BDAu;
    x0 += k0; x1 += k1;
    const int R0[4] = {13, 15, 26, 6};
    const int R1[4] = {17, 29, 16, 24};
#pragma unroll
    for (int i = 0; i < 5; i++) {
#pragma unroll
        for (int r = 0; r < 4; r++) {
            int rr = ((i & 1) == 0) ? R0[r] : R1[r];
            x0 += x1;
            x1 = (x1 << rr) | (x1 >> (32 - rr));
            x1 ^= x0;
        }
        unsigned a0 = (i % 3 == 0) ? k1 : (i % 3 == 1) ? k2 : k0;
        unsigned a1 = (i % 3 == 0) ? k2 : (i % 3 == 1) ? k0 : k1;
        x0 += a0;
        x1 += a1 + (unsigned)(i + 1);
    }
    unsigned bits = x0 ^ x1;

    float f = __fadd_rn(__uint_as_float((bits >> 9) | 0x3f800000u), -1.0f);
    const float lo = -0.99999994f;
    float u = __fadd_rn(__fmul_rn(f, 2.0f), lo);
    u = fmaxf(u, lo);

    float w = -log1pf(-u * u);
    float p;
    if (w < 5.0f) {
        w -= 2.5f;
        p = 2.81022636e-08f;
        p = fmaf(p, w, 3.43273939e-07f);
        p = fmaf(p, w, -3.5233877e-06f);
        p = fmaf(p, w, -4.39150654e-06f);
        p = fmaf(p, w, 0.00021858087f);
        p = fmaf(p, w, -0.00125372503f);
        p = fmaf(p, w, -0.00417768164f);
        p = fmaf(p, w, 0.246640727f);
        p = fmaf(p, w, 1.50140941f);
    } else {
        w = sqrtf(w) - 3.0f;
        p = -0.000200214257f;
        p = fmaf(p, w, 0.000100950558f);
        p = fmaf(p, w, 0.00134934322f);
        p = fmaf(p, w, -0.00367342844f);
        p = fmaf(p, w, 0.00573950773f);
        p = fmaf(p, w, -0.0076224613f);
        p = fmaf(p, w, 0.00943887047f);
        p = fmaf(p, w, 1.00167406f);
        p = fmaf(p, w, 2.83297682f);
    }
    return 1.41421356f * (p * u);
}

// ---------------- kernels ----------------
__global__ void k_zero() {
    int i = blockIdx.x * blockDim.x + threadIdx.x;
    const int tot = (Nn + Nn * Hd) / 4;
    if (i < tot) {
        float4 z = make_float4(0.f, 0.f, 0.f, 0.f);
        if (i < Nn / 4) ((float4*)g_agg1)[i] = z;
        else            ((float4*)g_agg2)[i - Nn / 4] = z;
    }
}

// conv1 edge: 4 edges/thread; ea via 7x LDG.128, ei via 2x int4
__global__ void k_conv1_edge(const float* __restrict__ x, const int* __restrict__ ei,
                             const float* __restrict__ ea, const float* __restrict__ We1,
                             const float* __restrict__ be1) {
    int g4 = blockIdx.x * blockDim.x + threadIdx.x;
    if (g4 >= Ee / 4) return;
    int e0 = g4 * 4;

    float w[EAd];
#pragma unroll
    for (int i = 0; i < EAd; i++) w[i] = __ldg(We1 + i);
    float be = __ldg(be1);

    float A[28];
    const float4* ap = (const float4*)(ea + (long long)e0 * EAd);
#pragma unroll
    for (int i = 0; i < 7; i++) *((float4*)&A[i * 4]) = __ldg(ap + i);

    int4 ss = *(const int4*)(ei + e0);
    int4 dd = *(const int4*)(ei + Ee + e0);
    int sv[4] = {ss.x, ss.y, ss.z, ss.w};
    int dv[4] = {dd.x, dd.y, dd.z, dd.w};

#pragma unroll
    for (int j = 0; j < 4; j++) {
        float acc = be;
#pragma unroll
        for (int i = 0; i < EAd; i++) acc = fmaf(A[j * EAd + i], w[i], acc);
        float m = fmaxf(__ldg(x + sv[j]) + acc, 0.f);
        atomicAdd(&g_agg1[dv[j]], m);
    }
}

// conv1 node MLP: 16 nodes/block, weight column loaded once
__global__ void k_conv1_mlp(const float* __restrict__ x, const float* __restrict__ W11,
                            const float* __restrict__ b11, const float* __restrict__ W12,
                            const float* __restrict__ b12, const float* __restrict__ eps1) {
    __shared__ float tS[16 * Hd];
    int k = threadIdx.x;  // 64
    float wcol[Hd];
#pragma unroll
    for (int j = 0; j < Hd; j++) wcol[j] = __ldg(W12 + j * Hd + k);

    int n0 = blockIdx.x * 16;
    float ep = 1.f + *eps1;
    float w11k = __ldg(W11 + k), b11k = __ldg(b11 + k);
#pragma unroll
    for (int i = 0; i < 16; i++) {
        float a = ep * __ldg(x + n0 + i) + g_agg1[n0 + i];
        tS[i * Hd + k] = fmaxf(a * w11k + b11k, 0.f);
    }
    __syncthreads();
    float bk = __ldg(b12 + k);
#pragma unroll
    for (int g = 0; g < 2; g++) {
        float acc[8];
#pragma unroll
        for (int i = 0; i < 8; i++) acc[i] = bk;
#pragma unroll
        for (int jq = 0; jq < Hd / 4; jq++) {
#pragma unroll
            for (int i = 0; i < 8; i++) {
                float4 v = *(const float4*)&tS[(g * 8 + i) * Hd + jq * 4];
                acc[i] = fmaf(v.x, wcol[jq * 4 + 0], acc[i]);
                acc[i] = fmaf(v.y, wcol[jq * 4 + 1], acc[i]);
                acc[i] = fmaf(v.z, wcol[jq * 4 + 2], acc[i]);
                acc[i] = fmaf(v.w, wcol[jq * 4 + 3], acc[i]);
            }
        }
#pragma unroll
        for (int i = 0; i < 8; i++)
            g_h1[(long long)(n0 + g * 8 + i) * Hd + k] = fmaxf(acc[i], 0.f);
    }
}

// conv2 edge v5: 16 lanes/edge, float4 weights/RED (R6 shape), ea lane-split + shfl
__global__ void __launch_bounds__(256, 4) k_conv2_edge(
        const int* __restrict__ ei, const float* __restrict__ ea,
        const float* __restrict__ We2, const float* __restrict__ be2) {
    int t = threadIdx.x;  // 256
    int lane = t & 15;
    int wb = t & 16;      // base of this 16-lane group within its warp
    int c0 = lane * 4;
    float4 wr[EAd];
#pragma unroll
    for (int i = 0; i < EAd; i++) wr[i] = *(const float4*)&We2[i * Hd + c0];
    float4 br = *(const float4*)&be2[c0];

    const unsigned FULL = 0xFFFFFFFFu;
    int group = (blockIdx.x * 256 + t) >> 4;
    int nGroups = (gridDim.x * 256) >> 4;
    for (int e = group;; e += nGroups) {
        bool active = (e < Ee);
        if (!__any_sync(FULL, active)) break;
        int ec = active ? e : 0;
        int s = __ldg(ei + ec);
        int d = __ldg(ei + Ee + ec);
        // lane-parallel edge-attr load: lanes 0..6 of each 16-lane group
        float av_mine = 0.f;
        if (lane < EAd) av_mine = __ldg(ea + (long long)ec * EAd + lane);
        float4 p = br;
#pragma unroll
        for (int i = 0; i < EAd; i++) {
            float av = __shfl_sync(FULL, av_mine, wb + i, 32);
            p.x = fmaf(av, wr[i].x, p.x);
            p.y = fmaf(av, wr[i].y, p.y);
            p.z = fmaf(av, wr[i].z, p.z);
            p.w = fmaf(av, wr[i].w, p.w);
        }
        float4 h = *(const float4*)(g_h1 + (long long)s * Hd + c0);
        float4 m;
        m.x = fmaxf(h.x + p.x, 0.f);
        m.y = fmaxf(h.y + p.y, 0.f);
        m.z = fmaxf(h.z + p.z, 0.f);
        m.w = fmaxf(h.w + p.w, 0.f);
        if (active) {
            float* dst = g_agg2 + (long long)d * Hd + c0;
            asm volatile("red.global.add.v4.f32 [%0], {%1,%2,%3,%4};"
                         :: "l"(dst), "f"(m.x), "f"(m.y), "f"(m.z), "f"(m.w) : "memory");
        }
    }
}

// conv2 node MLP + heads: 16 nodes/block
__global__ void k_conv2_mlp(const float* __restrict__ W21, const float* __restrict__ b21,
                            const float* __restrict__ W22, const float* __restrict__ b22,
                            const float* __restrict__ eps2, const float* __restrict__ Wmu,
                            const float* __restrict__ bmu, const float* __restrict__ Wlv,
                            const float* __restrict__ blv, float* __restrict__ outz,
                            float* __restrict__ outmu, float* __restrict__ outlv) {
    __shared__ float bufA[16 * Hd];
    __shared__ float bufB[16 * Hd];
    int k = threadIdx.x;  // 64
    int n0 = blockIdx.x * 16;
    float ep = 1.f + *eps2;

    float wcol[Hd];
#pragma unroll
    for (int j = 0; j < Hd; j++) wcol[j] = __ldg(W21 + j * Hd + k);

#pragma unroll
    for (int i = 0; i < 16; i++) {
        long long o = (long long)(n0 + i) * Hd + k;
        bufA[i * Hd + k] = ep * g_h1[o] + g_agg2[o];
    }
    __syncthreads();

    // stage 1: bufB = relu(bufA @ W21 + b21)
    {
        float b = __ldg(b21 + k);
#pragma unroll
        for (int g = 0; g < 2; g++) {
            float acc[8];
#pragma unroll
            for (int i = 0; i < 8; i++) acc[i] = b;
#pragma unroll
            for (int jq = 0; jq < Hd / 4; jq++) {
#pragma unroll
                for (int i = 0; i < 8; i++) {
                    float4 v = *(const float4*)&bufA[(g * 8 + i) * Hd + jq * 4];
                    acc[i] = fmaf(v.x, wcol[jq * 4 + 0], acc[i]);
                    acc[i] = fmaf(v.y, wcol[jq * 4 + 1], acc[i]);
                    acc[i] = fmaf(v.z, wcol[jq * 4 + 2], acc[i]);
                    acc[i] = fmaf(v.w, wcol[jq * 4 + 3], acc[i]);
                }
            }
#pragma unroll
            for (int i = 0; i < 8; i++) bufB[(g * 8 + i) * Hd + k] = fmaxf(acc[i], 0.f);
        }
    }
#pragma unroll
    for (int j = 0; j < Hd; j++) wcol[j] = __ldg(W22 + j * Hd + k);
    __syncthreads();

    // stage 2: bufA = relu(bufB @ W22 + b22)  (h2)
    {
        float b = __ldg(b22 + k);
#pragma unroll
        for (int g = 0; g < 2; g++) {
            float acc[8];
#pragma unroll
            for (int i = 0; i < 8; i++) acc[i] = b;
#pragma unroll
            for (int jq = 0; jq < Hd / 4; jq++) {
#pragma unroll
                for (int i = 0; i < 8; i++) {
                    float4 v = *(const float4*)&bufB[(g * 8 + i) * Hd + jq * 4];
                    acc[i] = fmaf(v.x, wcol[jq * 4 + 0], acc[i]);
                    acc[i] = fmaf(v.y, wcol[jq * 4 + 1], acc[i]);
                    acc[i] = fmaf(v.z, wcol[jq * 4 + 2], acc[i]);
                    acc[i] = fmaf(v.w, wcol[jq * 4 + 3], acc[i]);
                }
            }
            // write after a sync point below; safe to write now since stage1's reads of bufA done pre-sync
#pragma unroll
            for (int i = 0; i < 8; i++) bufA[(g * 8 + i) * Hd + k] = fmaxf(acc[i], 0.f);
        }
    }

    // heads
    int l = k & 31;
    const float* Wh = (k < 32) ? Wmu : Wlv;
#pragma unroll
    for (int j = 0; j < Hd; j++) wcol[j] = __ldg(Wh + j * Ld + l);
    __syncthreads();

    {
        float b = (k < 32) ? __ldg(bmu + l) : __ldg(blv + l);
        float* oph = (k < 32) ? outmu : outlv;
#pragma unroll
        for (int g = 0; g < 2; g++) {
            float acc[8];
#pragma unroll
            for (int i = 0; i < 8; i++) acc[i] = b;
#pragma unroll
            for (int jq = 0; jq < Hd / 4; jq++) {
#pragma unroll
                for (int i = 0; i < 8; i++) {
                    float4 v = *(const float4*)&bufA[(g * 8 + i) * Hd + jq * 4];
                    acc[i] = fmaf(v.x, wcol[jq * 4 + 0], acc[i]);
                    acc[i] = fmaf(v.y, wcol[jq * 4 + 1], acc[i]);
                    acc[i] = fmaf(v.z, wcol[jq * 4 + 2], acc[i]);
                    acc[i] = fmaf(v.w, wcol[jq * 4 + 3], acc[i]);
                }
            }
#pragma unroll
            for (int i = 0; i < 8; i++) {
                bufB[(g * 8 + i) * Hd + k] = acc[i];
                oph[(long long)(n0 + g * 8 + i) * Ld + l] = acc[i];
            }
        }
    }
    __syncthreads();

    if (k < 32) {
#pragma unroll
        for (int i = 0; i < 16; i++) {
            float mu = bufB[i * Hd + k];
            float lv = bufB[i * Hd + 32 + k];
            unsigned j = (unsigned)((n0 + i) * Ld + k);
            float z = mu + tf_normal(j) * expf(0.5f * lv);
            outz[(long long)(n0 + i) * Ld + k] = z;
        }
    }
}

// pooling + classifier
__global__ void k_pool(const float* __restrict__ z, const int* __restrict__ batch,
                       const float* __restrict__ Wc, const float* __restrict__ bc,
                       float* __restrict__ logits) {
    int g = blockIdx.x;
    int k = threadIdx.x;  // 32
    __shared__ float emb[Ld];
    __shared__ int bounds[2];
    if (k < 2) {
        int target = g + k;
        int lo = 0, hi = Nn;
        while (lo < hi) {
            int mid = (lo + hi) >> 1;
            if (batch[mid] < target) lo = mid + 1; else hi = mid;
        }
        bounds[k] = lo;
    }
    __syncthreads();
    int s = bounds[0], e = bounds[1];
    float acc = 0.f;
    for (int n = s; n < e; n++) acc += z[(long long)n * Ld + k];
    float cnt = (float)(e - s);
    emb[k] = acc / fmaxf(cnt, 1.f);
    __syncthreads();
    if (k < Cc) {
        float o = __ldg(bc + k);
#pragma unroll
        for (int l = 0; l < Ld; l++) o += emb[l] * __ldg(Wc + l * Cc + k);
        logits[g * Cc + k] = o;
    }
}

// ---------------- launcher ----------------
extern "C" void kernel_launch(void* const* d_in, const int* in_sizes, int n_in,
                              void* d_out, int out_size) {
    const float* x     = (const float*)d_in[0];
    const int*   ei    = (const int*)d_in[1];
    const float* ea    = (const float*)d_in[2];
    const int*   batch = (const int*)d_in[3];
    const float* We1 = (const float*)d_in[4];
    const float* be1 = (const float*)d_in[5];
    const float* W11 = (const float*)d_in[6];
    const float* b11 = (const float*)d_in[7];
    const float* W12 = (const float*)d_in[8];
    const float* b12 = (const float*)d_in[9];
    const float* eps1 = (const float*)d_in[10];
    const float* We2 = (const float*)d_in[11];
    const float* be2 = (const float*)d_in[12];
    const float* W21 = (const float*)d_in[13];
    const float* b21 = (const float*)d_in[14];
    const float* W22 = (const float*)d_in[15];
    const float* b22 = (const float*)d_in[16];
    const float* eps2 = (const float*)d_in[17];
    const float* Wmu = (const float*)d_in[18];
    const float* bmu = (const float*)d_in[19];
    const float* Wlv = (const float*)d_in[20];
    const float* blv = (const float*)d_in[21];
    const float* Wc  = (const float*)d_in[22];
    const float* bc  = (const float*)d_in[23];

    float* out = (float*)d_out;
    float* dz  = out;
    float* dmu = out + (size_t)Nn * Ld;
    float* dlv = out + (size_t)2 * Nn * Ld;
    float* dlg = out + (size_t)3 * Nn * Ld;

    const int ztot = (Nn + Nn * Hd) / 4;
    k_zero<<<(ztot + 255) / 256, 256>>>();
    k_conv1_edge<<<(Ee / 4 + 255) / 256, 256>>>(x, ei, ea, We1, be1);
    k_conv1_mlp<<<Nn / 16, Hd>>>(x, W11, b11, W12, b12, eps1);
    k_conv2_edge<<<592, 256>>>(ei, ea, We2, be2);
    k_conv2_mlp<<<Nn / 16, Hd>>>(W21, b21, W22, b22, eps2, Wmu, bmu, Wlv, blv, dz, dmu, dlv);
    k_pool<<<Gg, Ld>>>(dz, batch, Wc, bc, dlg);
}

// round 9
// speedup vs baseline: 1.3507x; 1.2474x over previous
#include <cuda_runtime.h>
#include <stdint.h>

#define Nn 100000
#define Ee 1600000
#define EAd 7
#define Hd 64
#define Ld 32
#define Gg 512
#define Cc 6

// ---------------- scratch ----------------
__device__ __align__(256) float g_agg1[Nn];
__device__ __align__(256) float g_h1[Nn * Hd];
__device__ __align__(256) float g_agg2[Nn * Hd];

// ---------------- Threefry-2x32 partitionable (JAX >= 0.4.36 default) ----------------
__device__ __forceinline__ float tf_normal(unsigned j) {
    unsigned x0 = 0u;       // counts_hi
    unsigned x1 = j;        // counts_lo
    const unsigned k0 = 0u, k1 = 42u;
    const unsigned k2 = k0 ^ k1 ^ 0x1BD11BDAu;
    x0 += k0; x1 += k1;
    const int R0[4] = {13, 15, 26, 6};
    const int R1[4] = {17, 29, 16, 24};
#pragma unroll
    for (int i = 0; i < 5; i++) {
#pragma unroll
        for (int r = 0; r < 4; r++) {
            int rr = ((i & 1) == 0) ? R0[r] : R1[r];
            x0 += x1;
            x1 = (x1 << rr) | (x1 >> (32 - rr));
            x1 ^= x0;
        }
        unsigned a0 = (i % 3 == 0) ? k1 : (i % 3 == 1) ? k2 : k0;
        unsigned a1 = (i % 3 == 0) ? k2 : (i % 3 == 1) ? k0 : k1;
        x0 += a0;
        x1 += a1 + (unsigned)(i + 1);
    }
    unsigned bits = x0 ^ x1;

    float f = __fadd_rn(__uint_as_float((bits >> 9) | 0x3f800000u), -1.0f);
    const float lo = -0.99999994f;
    float u = __fadd_rn(__fmul_rn(f, 2.0f), lo);
    u = fmaxf(u, lo);

    float w = -log1pf(-u * u);
    float p;
    if (w < 5.0f) {
        w -= 2.5f;
        p = 2.81022636e-08f;
        p = fmaf(p, w, 3.43273939e-07f);
        p = fmaf(p, w, -3.5233877e-06f);
        p = fmaf(p, w, -4.39150654e-06f);
        p = fmaf(p, w, 0.00021858087f);
        p = fmaf(p, w, -0.00125372503f);
        p = fmaf(p, w, -0.00417768164f);
        p = fmaf(p, w, 0.246640727f);
        p = fmaf(p, w, 1.50140941f);
    } else {
        w = sqrtf(w) - 3.0f;
        p = -0.000200214257f;
        p = fmaf(p, w, 0.000100950558f);
        p = fmaf(p, w, 0.00134934322f);
        p = fmaf(p, w, -0.00367342844f);
        p = fmaf(p, w, 0.00573950773f);
        p = fmaf(p, w, -0.0076224613f);
        p = fmaf(p, w, 0.00943887047f);
        p = fmaf(p, w, 1.00167406f);
        p = fmaf(p, w, 2.83297682f);
    }
    return 1.41421356f * (p * u);
}

// ---------------- kernels ----------------
__global__ void k_zero() {
    int i = blockIdx.x * blockDim.x + threadIdx.x;
    const int tot = (Nn + Nn * Hd) / 4;
    if (i < tot) {
        float4 z = make_float4(0.f, 0.f, 0.f, 0.f);
        if (i < Nn / 4) ((float4*)g_agg1)[i] = z;
        else            ((float4*)g_agg2)[i - Nn / 4] = z;
    }
}

// conv1 edge: 4 edges/thread; ea via 7x LDG.128, ei via 2x int4
__global__ void k_conv1_edge(const float* __restrict__ x, const int* __restrict__ ei,
                             const float* __restrict__ ea, const float* __restrict__ We1,
                             const float* __restrict__ be1) {
    int g4 = blockIdx.x * blockDim.x + threadIdx.x;
    if (g4 >= Ee / 4) return;
    int e0 = g4 * 4;

    float w[EAd];
#pragma unroll
    for (int i = 0; i < EAd; i++) w[i] = __ldg(We1 + i);
    float be = __ldg(be1);

    float A[28];
    const float4* ap = (const float4*)(ea + (long long)e0 * EAd);
#pragma unroll
    for (int i = 0; i < 7; i++) *((float4*)&A[i * 4]) = __ldg(ap + i);

    int4 ss = *(const int4*)(ei + e0);
    int4 dd = *(const int4*)(ei + Ee + e0);
    int sv[4] = {ss.x, ss.y, ss.z, ss.w};
    int dv[4] = {dd.x, dd.y, dd.z, dd.w};

#pragma unroll
    for (int j = 0; j < 4; j++) {
        float acc = be;
#pragma unroll
        for (int i = 0; i < EAd; i++) acc = fmaf(A[j * EAd + i], w[i], acc);
        float m = fmaxf(__ldg(x + sv[j]) + acc, 0.f);
        atomicAdd(&g_agg1[dv[j]], m);
    }
}

// conv1 node MLP: 16 nodes/block, weight column loaded once
__global__ void k_conv1_mlp(const float* __restrict__ x, const float* __restrict__ W11,
                            const float* __restrict__ b11, const float* __restrict__ W12,
                            const float* __restrict__ b12, const float* __restrict__ eps1) {
    __shared__ float tS[16 * Hd];
    int k = threadIdx.x;  // 64
    float wcol[Hd];
#pragma unroll
    for (int j = 0; j < Hd; j++) wcol[j] = __ldg(W12 + j * Hd + k);

    int n0 = blockIdx.x * 16;
    float ep = 1.f + *eps1;
    float w11k = __ldg(W11 + k), b11k = __ldg(b11 + k);
#pragma unroll
    for (int i = 0; i < 16; i++) {
        float a = ep * __ldg(x + n0 + i) + g_agg1[n0 + i];
        tS[i * Hd + k] = fmaxf(a * w11k + b11k, 0.f);
    }
    __syncthreads();
    float bk = __ldg(b12 + k);
#pragma unroll
    for (int g = 0; g < 2; g++) {
        float acc[8];
#pragma unroll
        for (int i = 0; i < 8; i++) acc[i] = bk;
#pragma unroll
        for (int jq = 0; jq < Hd / 4; jq++) {
#pragma unroll
            for (int i = 0; i < 8; i++) {
                float4 v = *(const float4*)&tS[(g * 8 + i) * Hd + jq * 4];
                acc[i] = fmaf(v.x, wcol[jq * 4 + 0], acc[i]);
                acc[i] = fmaf(v.y, wcol[jq * 4 + 1], acc[i]);
                acc[i] = fmaf(v.z, wcol[jq * 4 + 2], acc[i]);
                acc[i] = fmaf(v.w, wcol[jq * 4 + 3], acc[i]);
            }
        }
#pragma unroll
        for (int i = 0; i < 8; i++)
            g_h1[(long long)(n0 + g * 8 + i) * Hd + k] = fmaxf(acc[i], 0.f);
    }
}

// conv2 edge v6: R6 dataflow (16 lanes/edge, float4, per-lane ea loads)
// + software pipeline: prefetch next edge's indices and h1 gather
__global__ void __launch_bounds__(256, 4) k_conv2_edge(
        const int* __restrict__ ei, const float* __restrict__ ea,
        const float* __restrict__ We2, const float* __restrict__ be2) {
    int t = threadIdx.x;  // 256
    int lane = t & 15;
    int c0 = lane * 4;
    float4 wr[EAd];
#pragma unroll
    for (int i = 0; i < EAd; i++) wr[i] = *(const float4*)&We2[i * Hd + c0];
    float4 br = *(const float4*)&be2[c0];

    int group = (blockIdx.x * 256 + t) >> 4;
    int nGroups = (gridDim.x * 256) >> 4;

    int e = group;
    if (e >= Ee) return;
    int d = __ldg(ei + Ee + e);
    float4 h;
    {
        int s = __ldg(ei + e);
        h = *(const float4*)(g_h1 + (long long)s * Hd + c0);
    }
    while (true) {
        int en = e + nGroups;
        bool has_next = (en < Ee);
        int dn = 0;
        float4 hn = make_float4(0.f, 0.f, 0.f, 0.f);
        if (has_next) {
            int sn = __ldg(ei + en);
            dn = __ldg(ei + Ee + en);
            hn = *(const float4*)(g_h1 + (long long)sn * Hd + c0);
        }

        float4 p = br;
        const float* a = ea + (long long)e * EAd;
#pragma unroll
        for (int i = 0; i < EAd; i++) {
            float av = __ldg(a + i);
            p.x = fmaf(av, wr[i].x, p.x);
            p.y = fmaf(av, wr[i].y, p.y);
            p.z = fmaf(av, wr[i].z, p.z);
            p.w = fmaf(av, wr[i].w, p.w);
        }
        float4 m;
        m.x = fmaxf(h.x + p.x, 0.f);
        m.y = fmaxf(h.y + p.y, 0.f);
        m.z = fmaxf(h.z + p.z, 0.f);
        m.w = fmaxf(h.w + p.w, 0.f);
        float* dst = g_agg2 + (long long)d * Hd + c0;
        asm volatile("red.global.add.v4.f32 [%0], {%1,%2,%3,%4};"
                     :: "l"(dst), "f"(m.x), "f"(m.y), "f"(m.z), "f"(m.w) : "memory");

        if (!has_next) break;
        e = en; d = dn; h = hn;
    }
}

// conv2 node MLP + heads: 16 nodes/block
__global__ void k_conv2_mlp(const float* __restrict__ W21, const float* __restrict__ b21,
                            const float* __restrict__ W22, const float* __restrict__ b22,
                            const float* __restrict__ eps2, const float* __restrict__ Wmu,
                            const float* __restrict__ bmu, const float* __restrict__ Wlv,
                            const float* __restrict__ blv, float* __restrict__ outz,
                            float* __restrict__ outmu, float* __restrict__ outlv) {
    __shared__ float bufA[16 * Hd];
    __shared__ float bufB[16 * Hd];
    int k = threadIdx.x;  // 64
    int n0 = blockIdx.x * 16;
    float ep = 1.f + *eps2;

    float wcol[Hd];
#pragma unroll
    for (int j = 0; j < Hd; j++) wcol[j] = __ldg(W21 + j * Hd + k);

#pragma unroll
    for (int i = 0; i < 16; i++) {
        long long o = (long long)(n0 + i) * Hd + k;
        bufA[i * Hd + k] = ep * g_h1[o] + g_agg2[o];
    }
    __syncthreads();

    // stage 1: bufB = relu(bufA @ W21 + b21)
    {
        float b = __ldg(b21 + k);
#pragma unroll
        for (int g = 0; g < 2; g++) {
            float acc[8];
#pragma unroll
            for (int i = 0; i < 8; i++) acc[i] = b;
#pragma unroll
            for (int jq = 0; jq < Hd / 4; jq++) {
#pragma unroll
                for (int i = 0; i < 8; i++) {
                    float4 v = *(const float4*)&bufA[(g * 8 + i) * Hd + jq * 4];
                    acc[i] = fmaf(v.x, wcol[jq * 4 + 0], acc[i]);
                    acc[i] = fmaf(v.y, wcol[jq * 4 + 1], acc[i]);
                    acc[i] = fmaf(v.z, wcol[jq * 4 + 2], acc[i]);
                    acc[i] = fmaf(v.w, wcol[jq * 4 + 3], acc[i]);
                }
            }
#pragma unroll
            for (int i = 0; i < 8; i++) bufB[(g * 8 + i) * Hd + k] = fmaxf(acc[i], 0.f);
        }
    }
#pragma unroll
    for (int j = 0; j < Hd; j++) wcol[j] = __ldg(W22 + j * Hd + k);
    __syncthreads();

    // stage 2: bufA = relu(bufB @ W22 + b22)  (h2)
    {
        float b = __ldg(b22 + k);
#pragma unroll
        for (int g = 0; g < 2; g++) {
            float acc[8];
#pragma unroll
            for (int i = 0; i < 8; i++) acc[i] = b;
#pragma unroll
            for (int jq = 0; jq < Hd / 4; jq++) {
#pragma unroll
                for (int i = 0; i < 8; i++) {
                    float4 v = *(const float4*)&bufB[(g * 8 + i) * Hd + jq * 4];
                    acc[i] = fmaf(v.x, wcol[jq * 4 + 0], acc[i]);
                    acc[i] = fmaf(v.y, wcol[jq * 4 + 1], acc[i]);
                    acc[i] = fmaf(v.z, wcol[jq * 4 + 2], acc[i]);
                    acc[i] = fmaf(v.w, wcol[jq * 4 + 3], acc[i]);
                }
            }
#pragma unroll
            for (int i = 0; i < 8; i++) bufA[(g * 8 + i) * Hd + k] = fmaxf(acc[i], 0.f);
        }
    }

    // heads
    int l = k & 31;
    const float* Wh = (k < 32) ? Wmu : Wlv;
#pragma unroll
    for (int j = 0; j < Hd; j++) wcol[j] = __ldg(Wh + j * Ld + l);
    __syncthreads();

    {
        float b = (k < 32) ? __ldg(bmu + l) : __ldg(blv + l);
        float* oph = (k < 32) ? outmu : outlv;
#pragma unroll
        for (int g = 0; g < 2; g++) {
            float acc[8];
#pragma unroll
            for (int i = 0; i < 8; i++) acc[i] = b;
#pragma unroll
            for (int jq = 0; jq < Hd / 4; jq++) {
#pragma unroll
                for (int i = 0; i < 8; i++) {
                    float4 v = *(const float4*)&bufA[(g * 8 + i) * Hd + jq * 4];
                    acc[i] = fmaf(v.x, wcol[jq * 4 + 0], acc[i]);
                    acc[i] = fmaf(v.y, wcol[jq * 4 + 1], acc[i]);
                    acc[i] = fmaf(v.z, wcol[jq * 4 + 2], acc[i]);
                    acc[i] = fmaf(v.w, wcol[jq * 4 + 3], acc[i]);
                }
            }
#pragma unroll
            for (int i = 0; i < 8; i++) {
                bufB[(g * 8 + i) * Hd + k] = acc[i];
                oph[(long long)(n0 + g * 8 + i) * Ld + l] = acc[i];
            }
        }
    }
    __syncthreads();

    if (k < 32) {
#pragma unroll
        for (int i = 0; i < 16; i++) {
            float mu = bufB[i * Hd + k];
            float lv = bufB[i * Hd + 32 + k];
            unsigned j = (unsigned)((n0 + i) * Ld + k);
            float z = mu + tf_normal(j) * expf(0.5f * lv);
            outz[(long long)(n0 + i) * Ld + k] = z;
        }
    }
}

// pooling + classifier
__global__ void k_pool(const float* __restrict__ z, const int* __restrict__ batch,
                       const float* __restrict__ Wc, const float* __restrict__ bc,
                       float* __restrict__ logits) {
    int g = blockIdx.x;
    int k = threadIdx.x;  // 32
    __shared__ float emb[Ld];
    __shared__ int bounds[2];
    if (k < 2) {
        int target = g + k;
        int lo = 0, hi = Nn;
        while (lo < hi) {
            int mid = (lo + hi) >> 1;
            if (batch[mid] < target) lo = mid + 1; else hi = mid;
        }
        bounds[k] = lo;
    }
    __syncthreads();
    int s = bounds[0], e = bounds[1];
    float acc = 0.f;
    for (int n = s; n < e; n++) acc += z[(long long)n * Ld + k];
    float cnt = (float)(e - s);
    emb[k] = acc / fmaxf(cnt, 1.f);
    __syncthreads();
    if (k < Cc) {
        float o = __ldg(bc + k);
#pragma unroll
        for (int l = 0; l < Ld; l++) o += emb[l] * __ldg(Wc + l * Cc + k);
        logits[g * Cc + k] = o;
    }
}

// ---------------- launcher ----------------
extern "C" void kernel_launch(void* const* d_in, const int* in_sizes, int n_in,
                              void* d_out, int out_size) {
    const float* x     = (const float*)d_in[0];
    const int*   ei    = (const int*)d_in[1];
    const float* ea    = (const float*)d_in[2];
    const int*   batch = (const int*)d_in[3];
    const float* We1 = (const float*)d_in[4];
    const float* be1 = (const float*)d_in[5];
    const float* W11 = (const float*)d_in[6];
    const float* b11 = (const float*)d_in[7];
    const float* W12 = (const float*)d_in[8];
    const float* b12 = (const float*)d_in[9];
    const float* eps1 = (const float*)d_in[10];
    const float* We2 = (const float*)d_in[11];
    const float* be2 = (const float*)d_in[12];
    const float* W21 = (const float*)d_in[13];
    const float* b21 = (const float*)d_in[14];
    const float* W22 = (const float*)d_in[15];
    const float* b22 = (const float*)d_in[16];
    const float* eps2 = (const float*)d_in[17];
    const float* Wmu = (const float*)d_in[18];
    const float* bmu = (const float*)d_in[19];
    const float* Wlv = (const float*)d_in[20];
    const float* blv = (const float*)d_in[21];
    const float* Wc  = (const float*)d_in[22];
    const float* bc  = (const float*)d_in[23];

    float* out = (float*)d_out;
    float* dz  = out;
    float* dmu = out + (size_t)Nn * Ld;
    float* dlv = out + (size_t)2 * Nn * Ld;
    float* dlg = out + (size_t)3 * Nn * Ld;

    const int ztot = (Nn + Nn * Hd) / 4;
    k_zero<<<(ztot + 255) / 256, 256>>>();
    k_conv1_edge<<<(Ee / 4 + 255) / 256, 256>>>(x, ei, ea, We1, be1);
    k_conv1_mlp<<<Nn / 16, Hd>>>(x, W11, b11, W12, b12, eps1);
    k_conv2_edge<<<592, 256>>>(ei, ea, We2, be2);
    k_conv2_mlp<<<Nn / 16, Hd>>>(W21, b21, W22, b22, eps2, Wmu, bmu, Wlv, blv, dz, dmu, dlv);
    k_pool<<<Gg, Ld>>>(dz, batch, Wc, bc, dlg);
}

// round 10
// speedup vs baseline: 1.4754x; 1.0923x over previous
#include <cuda_runtime.h>
#include <stdint.h>

#define Nn 100000
#define Ee 1600000
#define EAd 7
#define Hd 64
#define Ld 32
#define Gg 512
#define Cc 6
#define CH 256   // edges per staged chunk

// ---------------- scratch ----------------
__device__ __align__(256) float g_agg1[Nn];
__device__ __align__(256) float g_h1[Nn * Hd];
__device__ __align__(256) float g_agg2[Nn * Hd];

// ---------------- Threefry-2x32 partitionable (JAX >= 0.4.36 default) ----------------
__device__ __forceinline__ float tf_normal(unsigned j) {
    unsigned x0 = 0u;       // counts_hi
    unsigned x1 = j;        // counts_lo
    const unsigned k0 = 0u, k1 = 42u;
    const unsigned k2 = k0 ^ k1 ^ 0x1BD11BDAu;
    x0 += k0; x1 += k1;
    const int R0[4] = {13, 15, 26, 6};
    const int R1[4] = {17, 29, 16, 24};
#pragma unroll
    for (int i = 0; i < 5; i++) {
#pragma unroll
        for (int r = 0; r < 4; r++) {
            int rr = ((i & 1) == 0) ? R0[r] : R1[r];
            x0 += x1;
            x1 = (x1 << rr) | (x1 >> (32 - rr));
            x1 ^= x0;
        }
        unsigned a0 = (i % 3 == 0) ? k1 : (i % 3 == 1) ? k2 : k0;
        unsigned a1 = (i % 3 == 0) ? k2 : (i % 3 == 1) ? k0 : k1;
        x0 += a0;
        x1 += a1 + (unsigned)(i + 1);
    }
    unsigned bits = x0 ^ x1;

    float f = __fadd_rn(__uint_as_float((bits >> 9) | 0x3f800000u), -1.0f);
    const float lo = -0.99999994f;
    float u = __fadd_rn(__fmul_rn(f, 2.0f), lo);
    u = fmaxf(u, lo);

    float w = -log1pf(-u * u);
    float p;
    if (w < 5.0f) {
        w -= 2.5f;
        p = 2.81022636e-08f;
        p = fmaf(p, w, 3.43273939e-07f);
        p = fmaf(p, w, -3.5233877e-06f);
        p = fmaf(p, w, -4.39150654e-06f);
        p = fmaf(p, w, 0.00021858087f);
        p = fmaf(p, w, -0.00125372503f);
        p = fmaf(p, w, -0.00417768164f);
        p = fmaf(p, w, 0.246640727f);
        p = fmaf(p, w, 1.50140941f);
    } else {
        w = sqrtf(w) - 3.0f;
        p = -0.000200214257f;
        p = fmaf(p, w, 0.000100950558f);
        p = fmaf(p, w, 0.00134934322f);
        p = fmaf(p, w, -0.00367342844f);
        p = fmaf(p, w, 0.00573950773f);
        p = fmaf(p, w, -0.0076224613f);
        p = fmaf(p, w, 0.00943887047f);
        p = fmaf(p, w, 1.00167406f);
        p = fmaf(p, w, 2.83297682f);
    }
    return 1.41421356f * (p * u);
}

// ---------------- kernels ----------------
__global__ void k_zero() {
    int i = blockIdx.x * blockDim.x + threadIdx.x;
    const int tot = (Nn + Nn * Hd) / 4;
    if (i < tot) {
        float4 z = make_float4(0.f, 0.f, 0.f, 0.f);
        if (i < Nn / 4) ((float4*)g_agg1)[i] = z;
        else            ((float4*)g_agg2)[i - Nn / 4] = z;
    }
}

// conv1 edge: 4 edges/thread; ea via 7x LDG.128, ei via 2x int4
__global__ void k_conv1_edge(const float* __restrict__ x, const int* __restrict__ ei,
                             const float* __restrict__ ea, const float* __restrict__ We1,
                             const float* __restrict__ be1) {
    int g4 = blockIdx.x * blockDim.x + threadIdx.x;
    if (g4 >= Ee / 4) return;
    int e0 = g4 * 4;

    float w[EAd];
#pragma unroll
    for (int i = 0; i < EAd; i++) w[i] = __ldg(We1 + i);
    float be = __ldg(be1);

    float A[28];
    const float4* ap = (const float4*)(ea + (long long)e0 * EAd);
#pragma unroll
    for (int i = 0; i < 7; i++) *((float4*)&A[i * 4]) = __ldg(ap + i);

    int4 ss = *(const int4*)(ei + e0);
    int4 dd = *(const int4*)(ei + Ee + e0);
    int sv[4] = {ss.x, ss.y, ss.z, ss.w};
    int dv[4] = {dd.x, dd.y, dd.z, dd.w};

#pragma unroll
    for (int j = 0; j < 4; j++) {
        float acc = be;
#pragma unroll
        for (int i = 0; i < EAd; i++) acc = fmaf(A[j * EAd + i], w[i], acc);
        float m = fmaxf(__ldg(x + sv[j]) + acc, 0.f);
        atomicAdd(&g_agg1[dv[j]], m);
    }
}

// conv1 node MLP: 16 nodes/block, weight column loaded once
__global__ void k_conv1_mlp(const float* __restrict__ x, const float* __restrict__ W11,
                            const float* __restrict__ b11, const float* __restrict__ W12,
                            const float* __restrict__ b12, const float* __restrict__ eps1) {
    __shared__ float tS[16 * Hd];
    int k = threadIdx.x;  // 64
    float wcol[Hd];
#pragma unroll
    for (int j = 0; j < Hd; j++) wcol[j] = __ldg(W12 + j * Hd + k);

    int n0 = blockIdx.x * 16;
    float ep = 1.f + *eps1;
    float w11k = __ldg(W11 + k), b11k = __ldg(b11 + k);
#pragma unroll
    for (int i = 0; i < 16; i++) {
        float a = ep * __ldg(x + n0 + i) + g_agg1[n0 + i];
        tS[i * Hd + k] = fmaxf(a * w11k + b11k, 0.f);
    }
    __syncthreads();
    float bk = __ldg(b12 + k);
#pragma unroll
    for (int g = 0; g < 2; g++) {
        float acc[8];
#pragma unroll
        for (int i = 0; i < 8; i++) acc[i] = bk;
#pragma unroll
        for (int jq = 0; jq < Hd / 4; jq++) {
#pragma unroll
            for (int i = 0; i < 8; i++) {
                float4 v = *(const float4*)&tS[(g * 8 + i) * Hd + jq * 4];
                acc[i] = fmaf(v.x, wcol[jq * 4 + 0], acc[i]);
                acc[i] = fmaf(v.y, wcol[jq * 4 + 1], acc[i]);
                acc[i] = fmaf(v.z, wcol[jq * 4 + 2], acc[i]);
                acc[i] = fmaf(v.w, wcol[jq * 4 + 3], acc[i]);
            }
        }
#pragma unroll
        for (int i = 0; i < 8; i++)
            g_h1[(long long)(n0 + g * 8 + i) * Hd + k] = fmaxf(acc[i], 0.f);
    }
}

// conv2 edge v7: SMEM-staged ea/ei chunks + 16 lanes/edge + h1 prefetch pipeline
__global__ void __launch_bounds__(256, 4) k_conv2_edge(
        const int* __restrict__ ei, const float* __restrict__ ea,
        const float* __restrict__ We2, const float* __restrict__ be2) {
    __shared__ float sea[CH * EAd];  // 7168 B
    __shared__ int ssrc[CH];         // 1024 B
    __shared__ int sdst[CH];         // 1024 B
    int t = threadIdx.x;  // 256
    int lane = t & 15;
    int grp = t >> 4;     // 16 groups/block, 16 edges each
    int c0 = lane * 4;
    float4 wr[EAd];
#pragma unroll
    for (int i = 0; i < EAd; i++) wr[i] = *(const float4*)&We2[i * Hd + c0];
    float4 br = *(const float4*)&be2[c0];

    const int step = gridDim.x * CH;
    for (int base = blockIdx.x * CH; base < Ee; base += step) {
        __syncthreads();  // protect previous chunk's SMEM reads
        // cooperative staging (Ee % CH == 0 -> always full chunks)
        {
            const float4* gp = (const float4*)(ea + (long long)base * EAd);
#pragma unroll
            for (int i = t; i < CH * EAd / 4; i += 256)
                ((float4*)sea)[i] = __ldg(gp + i);
            if (t < CH / 4) {
                ((int4*)ssrc)[t] = __ldg((const int4*)(ei + base) + t);
                ((int4*)sdst)[t] = __ldg((const int4*)(ei + Ee + base) + t);
            }
        }
        __syncthreads();

        int eb = grp * 16;
        int d = sdst[eb];
        float4 h;
        {
            int s = ssrc[eb];
            h = *(const float4*)(g_h1 + (long long)s * Hd + c0);
        }
#pragma unroll
        for (int j = 0; j < 16; j++) {
            int dn = 0;
            float4 hn = h;
            if (j + 1 < 16) {
                int sn = ssrc[eb + j + 1];
                dn = sdst[eb + j + 1];
                hn = *(const float4*)(g_h1 + (long long)sn * Hd + c0);
            }
            const float* aa = &sea[(eb + j) * EAd];
            float4 p = br;
#pragma unroll
            for (int i = 0; i < EAd; i++) {
                float av = aa[i];
                p.x = fmaf(av, wr[i].x, p.x);
                p.y = fmaf(av, wr[i].y, p.y);
                p.z = fmaf(av, wr[i].z, p.z);
                p.w = fmaf(av, wr[i].w, p.w);
            }
            float4 m;
            m.x = fmaxf(h.x + p.x, 0.f);
            m.y = fmaxf(h.y + p.y, 0.f);
            m.z = fmaxf(h.z + p.z, 0.f);
            m.w = fmaxf(h.w + p.w, 0.f);
            float* dst = g_agg2 + (long long)d * Hd + c0;
            asm volatile("red.global.add.v4.f32 [%0], {%1,%2,%3,%4};"
                         :: "l"(dst), "f"(m.x), "f"(m.y), "f"(m.z), "f"(m.w) : "memory");
            d = dn; h = hn;
        }
    }
}

// conv2 node MLP + heads: 16 nodes/block
__global__ void k_conv2_mlp(const float* __restrict__ W21, const float* __restrict__ b21,
                            const float* __restrict__ W22, const float* __restrict__ b22,
                            const float* __restrict__ eps2, const float* __restrict__ Wmu,
                            const float* __restrict__ bmu, const float* __restrict__ Wlv,
                            const float* __restrict__ blv, float* __restrict__ outz,
                            float* __restrict__ outmu, float* __restrict__ outlv) {
    __shared__ float bufA[16 * Hd];
    __shared__ float bufB[16 * Hd];
    int k = threadIdx.x;  // 64
    int n0 = blockIdx.x * 16;
    float ep = 1.f + *eps2;

    float wcol[Hd];
#pragma unroll
    for (int j = 0; j < Hd; j++) wcol[j] = __ldg(W21 + j * Hd + k);

#pragma unroll
    for (int i = 0; i < 16; i++) {
        long long o = (long long)(n0 + i) * Hd + k;
        bufA[i * Hd + k] = ep * g_h1[o] + g_agg2[o];
    }
    __syncthreads();

    // stage 1: bufB = relu(bufA @ W21 + b21)
    {
        float b = __ldg(b21 + k);
#pragma unroll
        for (int g = 0; g < 2; g++) {
            float acc[8];
#pragma unroll
            for (int i = 0; i < 8; i++) acc[i] = b;
#pragma unroll
            for (int jq = 0; jq < Hd / 4; jq++) {
#pragma unroll
                for (int i = 0; i < 8; i++) {
                    float4 v = *(const float4*)&bufA[(g * 8 + i) * Hd + jq * 4];
                    acc[i] = fmaf(v.x, wcol[jq * 4 + 0], acc[i]);
                    acc[i] = fmaf(v.y, wcol[jq * 4 + 1], acc[i]);
                    acc[i] = fmaf(v.z, wcol[jq * 4 + 2], acc[i]);
                    acc[i] = fmaf(v.w, wcol[jq * 4 + 3], acc[i]);
                }
            }
#pragma unroll
            for (int i = 0; i < 8; i++) bufB[(g * 8 + i) * Hd + k] = fmaxf(acc[i], 0.f);
        }
    }
#pragma unroll
    for (int j = 0; j < Hd; j++) wcol[j] = __ldg(W22 + j * Hd + k);
    __syncthreads();

    // stage 2: bufA = relu(bufB @ W22 + b22)  (h2)
    {
        float b = __ldg(b22 + k);
#pragma unroll
        for (int g = 0; g < 2; g++) {
            float acc[8];
#pragma unroll
            for (int i = 0; i < 8; i++) acc[i] = b;
#pragma unroll
            for (int jq = 0; jq < Hd / 4; jq++) {
#pragma unroll
                for (int i = 0; i < 8; i++) {
                    float4 v = *(const float4*)&bufB[(g * 8 + i) * Hd + jq * 4];
                    acc[i] = fmaf(v.x, wcol[jq * 4 + 0], acc[i]);
                    acc[i] = fmaf(v.y, wcol[jq * 4 + 1], acc[i]);
                    acc[i] = fmaf(v.z, wcol[jq * 4 + 2], acc[i]);
                    acc[i] = fmaf(v.w, wcol[jq * 4 + 3], acc[i]);
                }
            }
#pragma unroll
            for (int i = 0; i < 8; i++) bufA[(g * 8 + i) * Hd + k] = fmaxf(acc[i], 0.f);
        }
    }

    // heads
    int l = k & 31;
    const float* Wh = (k < 32) ? Wmu : Wlv;
#pragma unroll
    for (int j = 0; j < Hd; j++) wcol[j] = __ldg(Wh + j * Ld + l);
    __syncthreads();

    {
        float b = (k < 32) ? __ldg(bmu + l) : __ldg(blv + l);
        float* oph = (k < 32) ? outmu : outlv;
#pragma unroll
        for (int g = 0; g < 2; g++) {
            float acc[8];
#pragma unroll
            for (int i = 0; i < 8; i++) acc[i] = b;
#pragma unroll
            for (int jq = 0; jq < Hd / 4; jq++) {
#pragma unroll
                for (int i = 0; i < 8; i++) {
                    float4 v = *(const float4*)&bufA[(g * 8 + i) * Hd + jq * 4];
                    acc[i] = fmaf(v.x, wcol[jq * 4 + 0], acc[i]);
                    acc[i] = fmaf(v.y, wcol[jq * 4 + 1], acc[i]);
                    acc[i] = fmaf(v.z, wcol[jq * 4 + 2], acc[i]);
                    acc[i] = fmaf(v.w, wcol[jq * 4 + 3], acc[i]);
                }
            }
#pragma unroll
            for (int i = 0; i < 8; i++) {
                bufB[(g * 8 + i) * Hd + k] = acc[i];
                oph[(long long)(n0 + g * 8 + i) * Ld + l] = acc[i];
            }
        }
    }
    __syncthreads();

    if (k < 32) {
#pragma unroll
        for (int i = 0; i < 16; i++) {
            float mu = bufB[i * Hd + k];
            float lv = bufB[i * Hd + 32 + k];
            unsigned j = (unsigned)((n0 + i) * Ld + k);
            float z = mu + tf_normal(j) * expf(0.5f * lv);
            outz[(long long)(n0 + i) * Ld + k] = z;
        }
    }
}

// pooling + classifier
__global__ void k_pool(const float* __restrict__ z, const int* __restrict__ batch,
                       const float* __restrict__ Wc, const float* __restrict__ bc,
                       float* __restrict__ logits) {
    int g = blockIdx.x;
    int k = threadIdx.x;  // 32
    __shared__ float emb[Ld];
    __shared__ int bounds[2];
    if (k < 2) {
        int target = g + k;
        int lo = 0, hi = Nn;
        while (lo < hi) {
            int mid = (lo + hi) >> 1;
            if (batch[mid] < target) lo = mid + 1; else hi = mid;
        }
        bounds[k] = lo;
    }
    __syncthreads();
    int s = bounds[0], e = bounds[1];
    float acc = 0.f;
    for (int n = s; n < e; n++) acc += z[(long long)n * Ld + k];
    float cnt = (float)(e - s);
    emb[k] = acc / fmaxf(cnt, 1.f);
    __syncthreads();
    if (k < Cc) {
        float o = __ldg(bc + k);
#pragma unroll
        for (int l = 0; l < Ld; l++) o += emb[l] * __ldg(Wc + l * Cc + k);
        logits[g * Cc + k] = o;
    }
}

// ---------------- launcher ----------------
extern "C" void kernel_launch(void* const* d_in, const int* in_sizes, int n_in,
                              void* d_out, int out_size) {
    const float* x     = (const float*)d_in[0];
    const int*   ei    = (const int*)d_in[1];
    const float* ea    = (const float*)d_in[2];
    const int*   batch = (const int*)d_in[3];
    const float* We1 = (const float*)d_in[4];
    const float* be1 = (const float*)d_in[5];
    const float* W11 = (const float*)d_in[6];
    const float* b11 = (const float*)d_in[7];
    const float* W12 = (const float*)d_in[8];
    const float* b12 = (const float*)d_in[9];
    const float* eps1 = (const float*)d_in[10];
    const float* We2 = (const float*)d_in[11];
    const float* be2 = (const float*)d_in[12];
    const float* W21 = (const float*)d_in[13];
    const float* b21 = (const float*)d_in[14];
    const float* W22 = (const float*)d_in[15];
    const float* b22 = (const float*)d_in[16];
    const float* eps2 = (const float*)d_in[17];
    const float* Wmu = (const float*)d_in[18];
    const float* bmu = (const float*)d_in[19];
    const float* Wlv = (const float*)d_in[20];
    const float* blv = (const float*)d_in[21];
    const float* Wc  = (const float*)d_in[22];
    const float* bc  = (const float*)d_in[23];

    float* out = (float*)d_out;
    float* dz  = out;
    float* dmu = out + (size_t)Nn * Ld;
    float* dlv = out + (size_t)2 * Nn * Ld;
    float* dlg = out + (size_t)3 * Nn * Ld;

    const int ztot = (Nn + Nn * Hd) / 4;
    k_zero<<<(ztot + 255) / 256, 256>>>();
    k_conv1_edge<<<(Ee / 4 + 255) / 256, 256>>>(x, ei, ea, We1, be1);
    k_conv1_mlp<<<Nn / 16, Hd>>>(x, W11, b11, W12, b12, eps1);
    k_conv2_edge<<<592, 256>>>(ei, ea, We2, be2);
    k_conv2_mlp<<<Nn / 16, Hd>>>(W21, b21, W22, b22, eps2, Wmu, bmu, Wlv, blv, dz, dmu, dlv);
    k_pool<<<Gg, Ld>>>(dz, batch, Wc, bc, dlg);
}

// round 11
// speedup vs baseline: 1.6068x; 1.0891x over previous
#include <cuda_runtime.h>
#include <stdint.h>

#define Nn 100000
#define Ee 1600000
#define EAd 7
#define Hd 64
#define Ld 32
#define Gg 512
#define Cc 6
#define CH 256   // edges per staged chunk

// ---------------- scratch ----------------
__device__ __align__(256) float g_agg1[Nn];
__device__ __align__(256) float g_h1[Nn * Hd];
__device__ __align__(256) float g_agg2[Nn * Hd];

// ---------------- Threefry-2x32 partitionable (JAX >= 0.4.36 default) ----------------
__device__ __forceinline__ float tf_normal(unsigned j) {
    unsigned x0 = 0u;       // counts_hi
    unsigned x1 = j;        // counts_lo
    const unsigned k0 = 0u, k1 = 42u;
    const unsigned k2 = k0 ^ k1 ^ 0x1BD11BDAu;
    x0 += k0; x1 += k1;
    const int R0[4] = {13, 15, 26, 6};
    const int R1[4] = {17, 29, 16, 24};
#pragma unroll
    for (int i = 0; i < 5; i++) {
#pragma unroll
        for (int r = 0; r < 4; r++) {
            int rr = ((i & 1) == 0) ? R0[r] : R1[r];
            x0 += x1;
            x1 = (x1 << rr) | (x1 >> (32 - rr));
            x1 ^= x0;
        }
        unsigned a0 = (i % 3 == 0) ? k1 : (i % 3 == 1) ? k2 : k0;
        unsigned a1 = (i % 3 == 0) ? k2 : (i % 3 == 1) ? k0 : k1;
        x0 += a0;
        x1 += a1 + (unsigned)(i + 1);
    }
    unsigned bits = x0 ^ x1;

    float f = __fadd_rn(__uint_as_float((bits >> 9) | 0x3f800000u), -1.0f);
    const float lo = -0.99999994f;
    float u = __fadd_rn(__fmul_rn(f, 2.0f), lo);
    u = fmaxf(u, lo);

    float w = -log1pf(-u * u);
    float p;
    if (w < 5.0f) {
        w -= 2.5f;
        p = 2.81022636e-08f;
        p = fmaf(p, w, 3.43273939e-07f);
        p = fmaf(p, w, -3.5233877e-06f);
        p = fmaf(p, w, -4.39150654e-06f);
        p = fmaf(p, w, 0.00021858087f);
        p = fmaf(p, w, -0.00125372503f);
        p = fmaf(p, w, -0.00417768164f);
        p = fmaf(p, w, 0.246640727f);
        p = fmaf(p, w, 1.50140941f);
    } else {
        w = sqrtf(w) - 3.0f;
        p = -0.000200214257f;
        p = fmaf(p, w, 0.000100950558f);
        p = fmaf(p, w, 0.00134934322f);
        p = fmaf(p, w, -0.00367342844f);
        p = fmaf(p, w, 0.00573950773f);
        p = fmaf(p, w, -0.0076224613f);
        p = fmaf(p, w, 0.00943887047f);
        p = fmaf(p, w, 1.00167406f);
        p = fmaf(p, w, 2.83297682f);
    }
    return 1.41421356f * (p * u);
}

// ---------------- kernels ----------------
__global__ void k_zero() {
    int i = blockIdx.x * blockDim.x + threadIdx.x;
    const int tot = (Nn + Nn * Hd) / 4;
    if (i < tot) {
        float4 z = make_float4(0.f, 0.f, 0.f, 0.f);
        if (i < Nn / 4) ((float4*)g_agg1)[i] = z;
        else            ((float4*)g_agg2)[i - Nn / 4] = z;
    }
}

// conv1 edge: 4 edges/thread; ea via 7x LDG.128, ei via 2x int4
__global__ void k_conv1_edge(const float* __restrict__ x, const int* __restrict__ ei,
                             const float* __restrict__ ea, const float* __restrict__ We1,
                             const float* __restrict__ be1) {
    int g4 = blockIdx.x * blockDim.x + threadIdx.x;
    if (g4 >= Ee / 4) return;
    int e0 = g4 * 4;

    float w[EAd];
#pragma unroll
    for (int i = 0; i < EAd; i++) w[i] = __ldg(We1 + i);
    float be = __ldg(be1);

    float A[28];
    const float4* ap = (const float4*)(ea + (long long)e0 * EAd);
#pragma unroll
    for (int i = 0; i < 7; i++) *((float4*)&A[i * 4]) = __ldg(ap + i);

    int4 ss = *(const int4*)(ei + e0);
    int4 dd = *(const int4*)(ei + Ee + e0);
    int sv[4] = {ss.x, ss.y, ss.z, ss.w};
    int dv[4] = {dd.x, dd.y, dd.z, dd.w};

#pragma unroll
    for (int j = 0; j < 4; j++) {
        float acc = be;
#pragma unroll
        for (int i = 0; i < EAd; i++) acc = fmaf(A[j * EAd + i], w[i], acc);
        float m = fmaxf(__ldg(x + sv[j]) + acc, 0.f);
        atomicAdd(&g_agg1[dv[j]], m);
    }
}

// conv1 node MLP: 16 nodes/block, 128 threads (two halves x 8 nodes)
__global__ void k_conv1_mlp(const float* __restrict__ x, const float* __restrict__ W11,
                            const float* __restrict__ b11, const float* __restrict__ W12,
                            const float* __restrict__ b12, const float* __restrict__ eps1) {
    __shared__ float tS[16 * Hd];
    int k = threadIdx.x & 63;
    int hh = threadIdx.x >> 6;   // 0/1
    float wcol[Hd];
#pragma unroll
    for (int j = 0; j < Hd; j++) wcol[j] = __ldg(W12 + j * Hd + k);

    int n0 = blockIdx.x * 16;
    int nb = n0 + hh * 8;
    float ep = 1.f + *eps1;
    float w11k = __ldg(W11 + k), b11k = __ldg(b11 + k);
#pragma unroll
    for (int i = 0; i < 8; i++) {
        float a = ep * __ldg(x + nb + i) + g_agg1[nb + i];
        tS[(hh * 8 + i) * Hd + k] = fmaxf(a * w11k + b11k, 0.f);
    }
    __syncthreads();
    float acc[8];
    float bk = __ldg(b12 + k);
#pragma unroll
    for (int i = 0; i < 8; i++) acc[i] = bk;
#pragma unroll
    for (int jq = 0; jq < Hd / 4; jq++) {
#pragma unroll
        for (int i = 0; i < 8; i++) {
            float4 v = *(const float4*)&tS[(hh * 8 + i) * Hd + jq * 4];
            acc[i] = fmaf(v.x, wcol[jq * 4 + 0], acc[i]);
            acc[i] = fmaf(v.y, wcol[jq * 4 + 1], acc[i]);
            acc[i] = fmaf(v.z, wcol[jq * 4 + 2], acc[i]);
            acc[i] = fmaf(v.w, wcol[jq * 4 + 3], acc[i]);
        }
    }
#pragma unroll
    for (int i = 0; i < 8; i++)
        g_h1[(long long)(nb + i) * Hd + k] = fmaxf(acc[i], 0.f);
}

// conv2 edge v7: SMEM-staged ea/ei chunks + 16 lanes/edge + h1 prefetch pipeline
__global__ void __launch_bounds__(256, 4) k_conv2_edge(
        const int* __restrict__ ei, const float* __restrict__ ea,
        const float* __restrict__ We2, const float* __restrict__ be2) {
    __shared__ float sea[CH * EAd];  // 7168 B
    __shared__ int ssrc[CH];         // 1024 B
    __shared__ int sdst[CH];         // 1024 B
    int t = threadIdx.x;  // 256
    int lane = t & 15;
    int grp = t >> 4;     // 16 groups/block, 16 edges each
    int c0 = lane * 4;
    float4 wr[EAd];
#pragma unroll
    for (int i = 0; i < EAd; i++) wr[i] = *(const float4*)&We2[i * Hd + c0];
    float4 br = *(const float4*)&be2[c0];

    const int step = gridDim.x * CH;
    for (int base = blockIdx.x * CH; base < Ee; base += step) {
        __syncthreads();  // protect previous chunk's SMEM reads
        {
            const float4* gp = (const float4*)(ea + (long long)base * EAd);
#pragma unroll
            for (int i = t; i < CH * EAd / 4; i += 256)
                ((float4*)sea)[i] = __ldg(gp + i);
            if (t < CH / 4) {
                ((int4*)ssrc)[t] = __ldg((const int4*)(ei + base) + t);
                ((int4*)sdst)[t] = __ldg((const int4*)(ei + Ee + base) + t);
            }
        }
        __syncthreads();

        int eb = grp * 16;
        int d = sdst[eb];
        float4 h;
        {
            int s = ssrc[eb];
            h = *(const float4*)(g_h1 + (long long)s * Hd + c0);
        }
#pragma unroll
        for (int j = 0; j < 16; j++) {
            int dn = 0;
            float4 hn = h;
            if (j + 1 < 16) {
                int sn = ssrc[eb + j + 1];
                dn = sdst[eb + j + 1];
                hn = *(const float4*)(g_h1 + (long long)sn * Hd + c0);
            }
            const float* aa = &sea[(eb + j) * EAd];
            float4 p = br;
#pragma unroll
            for (int i = 0; i < EAd; i++) {
                float av = aa[i];
                p.x = fmaf(av, wr[i].x, p.x);
                p.y = fmaf(av, wr[i].y, p.y);
                p.z = fmaf(av, wr[i].z, p.z);
                p.w = fmaf(av, wr[i].w, p.w);
            }
            float4 m;
            m.x = fmaxf(h.x + p.x, 0.f);
            m.y = fmaxf(h.y + p.y, 0.f);
            m.z = fmaxf(h.z + p.z, 0.f);
            m.w = fmaxf(h.w + p.w, 0.f);
            float* dst = g_agg2 + (long long)d * Hd + c0;
            asm volatile("red.global.add.v4.f32 [%0], {%1,%2,%3,%4};"
                         :: "l"(dst), "f"(m.x), "f"(m.y), "f"(m.z), "f"(m.w) : "memory");
            d = dn; h = hn;
        }
    }
}

// conv2 node MLP + heads: 16 nodes/block, 128 threads (two halves x 8 nodes)
__global__ void k_conv2_mlp(const float* __restrict__ W21, const float* __restrict__ b21,
                            const float* __restrict__ W22, const float* __restrict__ b22,
                            const float* __restrict__ eps2, const float* __restrict__ Wmu,
                            const float* __restrict__ bmu, const float* __restrict__ Wlv,
                            const float* __restrict__ blv, float* __restrict__ outz,
                            float* __restrict__ outmu, float* __restrict__ outlv) {
    __shared__ float bufA[16 * Hd];
    __shared__ float bufB[16 * Hd];
    int k = threadIdx.x & 63;
    int hh = threadIdx.x >> 6;   // 0/1
    int n0 = blockIdx.x * 16;
    int rb = hh * 8;             // row base in buffers
    int nb = n0 + rb;
    float ep = 1.f + *eps2;

    float wcol[Hd];
#pragma unroll
    for (int j = 0; j < Hd; j++) wcol[j] = __ldg(W21 + j * Hd + k);

#pragma unroll
    for (int i = 0; i < 8; i++) {
        long long o = (long long)(nb + i) * Hd + k;
        bufA[(rb + i) * Hd + k] = ep * g_h1[o] + g_agg2[o];
    }
    __syncthreads();

    float acc[8];
    // stage 1: bufB = relu(bufA @ W21 + b21)
    {
        float b = __ldg(b21 + k);
#pragma unroll
        for (int i = 0; i < 8; i++) acc[i] = b;
#pragma unroll
        for (int jq = 0; jq < Hd / 4; jq++) {
#pragma unroll
            for (int i = 0; i < 8; i++) {
                float4 v = *(const float4*)&bufA[(rb + i) * Hd + jq * 4];
                acc[i] = fmaf(v.x, wcol[jq * 4 + 0], acc[i]);
                acc[i] = fmaf(v.y, wcol[jq * 4 + 1], acc[i]);
                acc[i] = fmaf(v.z, wcol[jq * 4 + 2], acc[i]);
                acc[i] = fmaf(v.w, wcol[jq * 4 + 3], acc[i]);
            }
        }
#pragma unroll
        for (int i = 0; i < 8; i++) bufB[(rb + i) * Hd + k] = fmaxf(acc[i], 0.f);
    }
#pragma unroll
    for (int j = 0; j < Hd; j++) wcol[j] = __ldg(W22 + j * Hd + k);
    __syncthreads();

    // stage 2: bufA = relu(bufB @ W22 + b22)  (h2)
    {
        float b = __ldg(b22 + k);
#pragma unroll
        for (int i = 0; i < 8; i++) acc[i] = b;
#pragma unroll
        for (int jq = 0; jq < Hd / 4; jq++) {
#pragma unroll
            for (int i = 0; i < 8; i++) {
                float4 v = *(const float4*)&bufB[(rb + i) * Hd + jq * 4];
                acc[i] = fmaf(v.x, wcol[jq * 4 + 0], acc[i]);
                acc[i] = fmaf(v.y, wcol[jq * 4 + 1], acc[i]);
                acc[i] = fmaf(v.z, wcol[jq * 4 + 2], acc[i]);
                acc[i] = fmaf(v.w, wcol[jq * 4 + 3], acc[i]);
            }
        }
        __syncthreads();
#pragma unroll
        for (int i = 0; i < 8; i++) bufA[(rb + i) * Hd + k] = fmaxf(acc[i], 0.f);
    }

    // heads
    int l = k & 31;
    const float* Wh = (k < 32) ? Wmu : Wlv;
#pragma unroll
    for (int j = 0; j < Hd; j++) wcol[j] = __ldg(Wh + j * Ld + l);
    __syncthreads();

    {
        float b = (k < 32) ? __ldg(bmu + l) : __ldg(blv + l);
        float* oph = (k < 32) ? outmu : outlv;
#pragma unroll
        for (int i = 0; i < 8; i++) acc[i] = b;
#pragma unroll
        for (int jq = 0; jq < Hd / 4; jq++) {
#pragma unroll
            for (int i = 0; i < 8; i++) {
                float4 v = *(const float4*)&bufA[(rb + i) * Hd + jq * 4];
                acc[i] = fmaf(v.x, wcol[jq * 4 + 0], acc[i]);
                acc[i] = fmaf(v.y, wcol[jq * 4 + 1], acc[i]);
                acc[i] = fmaf(v.z, wcol[jq * 4 + 2], acc[i]);
                acc[i] = fmaf(v.w, wcol[jq * 4 + 3], acc[i]);
            }
        }
#pragma unroll
        for (int i = 0; i < 8; i++) {
            bufB[(rb + i) * Hd + k] = acc[i];
            oph[(long long)(nb + i) * Ld + l] = acc[i];
        }
    }
    __syncthreads();

    if (k < 32) {
#pragma unroll
        for (int i = 0; i < 8; i++) {
            float mu = bufB[(rb + i) * Hd + k];
            float lv = bufB[(rb + i) * Hd + 32 + k];
            unsigned j = (unsigned)((nb + i) * Ld + k);
            float z = mu + tf_normal(j) * expf(0.5f * lv);
            outz[(long long)(nb + i) * Ld + k] = z;
        }
    }
}

// pooling + classifier: 128 threads (4 warps stride the node range)
__global__ void k_pool(const float* __restrict__ z, const int* __restrict__ batch,
                       const float* __restrict__ Wc, const float* __restrict__ bc,
                       float* __restrict__ logits) {
    int g = blockIdx.x;
    int k = threadIdx.x & 31;   // column
    int w = threadIdx.x >> 5;   // warp 0..3
    __shared__ float part[4 * Ld];
    __shared__ float emb[Ld];
    __shared__ int bounds[2];
    if (threadIdx.x < 2) {
        int target = g + threadIdx.x;
        int lo = 0, hi = Nn;
        while (lo < hi) {
            int mid = (lo + hi) >> 1;
            if (batch[mid] < target) lo = mid + 1; else hi = mid;
        }
        bounds[threadIdx.x] = lo;
    }
    __syncthreads();
    int s = bounds[0], e = bounds[1];
    float acc = 0.f;
    for (int n = s + w; n < e; n += 4) acc += z[(long long)n * Ld + k];
    part[w * Ld + k] = acc;
    __syncthreads();
    if (w == 0) {
        float tot = part[k] + part[Ld + k] + part[2 * Ld + k] + part[3 * Ld + k];
        float cnt = (float)(e - s);
        emb[k] = tot / fmaxf(cnt, 1.f);
    }
    __syncthreads();
    if (threadIdx.x < Cc) {
        float o = __ldg(bc + threadIdx.x);
#pragma unroll
        for (int l = 0; l < Ld; l++) o += emb[l] * __ldg(Wc + l * Cc + threadIdx.x);
        logits[g * Cc + threadIdx.x] = o;
    }
}

// ---------------- launcher ----------------
extern "C" void kernel_launch(void* const* d_in, const int* in_sizes, int n_in,
                              void* d_out, int out_size) {
    const float* x     = (const float*)d_in[0];
    const int*   ei    = (const int*)d_in[1];
    const float* ea    = (const float*)d_in[2];
    const int*   batch = (const int*)d_in[3];
    const float* We1 = (const float*)d_in[4];
    const float* be1 = (const float*)d_in[5];
    const float* W11 = (const float*)d_in[6];
    const float* b11 = (const float*)d_in[7];
    const float* W12 = (const float*)d_in[8];
    const float* b12 = (const float*)d_in[9];
    const float* eps1 = (const float*)d_in[10];
    const float* We2 = (const float*)d_in[11];
    const float* be2 = (const float*)d_in[12];
    const float* W21 = (const float*)d_in[13];
    const float* b21 = (const float*)d_in[14];
    const float* W22 = (const float*)d_in[15];
    const float* b22 = (const float*)d_in[16];
    const float* eps2 = (const float*)d_in[17];
    const float* Wmu = (const float*)d_in[18];
    const float* bmu = (const float*)d_in[19];
    const float* Wlv = (const float*)d_in[20];
    const float* blv = (const float*)d_in[21];
    const float* Wc  = (const float*)d_in[22];
    const float* bc  = (const float*)d_in[23];

    float* out = (float*)d_out;
    float* dz  = out;
    float* dmu = out + (size_t)Nn * Ld;
    float* dlv = out + (size_t)2 * Nn * Ld;
    float* dlg = out + (size_t)3 * Nn * Ld;

    const int ztot = (Nn + Nn * Hd) / 4;
    k_zero<<<(ztot + 255) / 256, 256>>>();
    k_conv1_edge<<<(Ee / 4 + 255) / 256, 256>>>(x, ei, ea, We1, be1);
    k_conv1_mlp<<<Nn / 16, 128>>>(x, W11, b11, W12, b12, eps1);
    k_conv2_edge<<<592, 256>>>(ei, ea, We2, be2);
    k_conv2_mlp<<<Nn / 16, 128>>>(W21, b21, W22, b22, eps2, Wmu, bmu, Wlv, blv, dz, dmu, dlv);
    k_pool<<<Gg, 128>>>(dz, batch, Wc, bc, dlg);
}